// round 15
// baseline (speedup 1.0000x reference)
#include <cuda_runtime.h>
#include <cuda_bf16.h>
#include <cuda_fp16.h>
#include <math.h>
#include <stdint.h>

// Problem constants
#define BB 4
#define SS 2048
#define CC 512
#define HH 8
#define GG 32
#define DD 64
#define EPS 1e-3f

// Scratch (device globals; allocation-free per harness rules)
__device__ float g_mean[BB * GG];
__device__ float g_rstd[BB * GG];
__device__ __half g_xnh[(size_t)BB * SS * CC];        // fp16 normalized input
__device__ __half g_aoh[(size_t)BB * SS * CC];        // fp16 attention out
__device__ __half g_wqkvh[(size_t)CC * 3 * CC];       // [512 x 1536] fp16
__device__ __half g_wprojh[(size_t)CC * CC];          // [512 x 512] fp16
__device__ __half g_qh[(size_t)BB * HH * SS * DD];    // (pre-scaled by log2e/8)
__device__ __half g_kh[(size_t)BB * HH * SS * DD];
__device__ __half g_vh[(size_t)BB * HH * SS * DD];    // [bh][s][d]

// ---------------------------------------------------------------------------
// helpers
// ---------------------------------------------------------------------------
__device__ __forceinline__ void cp16(void* s, const void* g) {
    unsigned sa = (unsigned)__cvta_generic_to_shared(s);
    asm volatile("cp.async.cg.shared.global [%0], [%1], 16;\n" :: "r"(sa), "l"(g));
}
__device__ __forceinline__ void cp_commit() {
    asm volatile("cp.async.commit_group;\n");
}
__device__ __forceinline__ uint32_t pkh(float x, float y) {
    __half2 t = __floats2half2_rn(x, y);
    return *reinterpret_cast<uint32_t*>(&t);
}
__device__ __forceinline__ uint32_t ex2h2(uint32_t x) {
    uint32_t y;
    asm("ex2.approx.f16x2 %0, %1;\n" : "=r"(y) : "r"(x));
    return y;
}
__device__ __forceinline__ void mma16816h(float* c, const uint32_t* a, uint32_t b0, uint32_t b1) {
    asm volatile(
        "mma.sync.aligned.m16n8k16.row.col.f32.f16.f16.f32 "
        "{%0,%1,%2,%3},{%4,%5,%6,%7},{%8,%9},{%0,%1,%2,%3};\n"
        : "+f"(c[0]), "+f"(c[1]), "+f"(c[2]), "+f"(c[3])
        : "r"(a[0]), "r"(a[1]), "r"(a[2]), "r"(a[3]), "r"(b0), "r"(b1));
}
// f16-accum mma: C/D packed half2 x2 (reg0 = row g, reg1 = row g+8)
__device__ __forceinline__ void mma16816hh(uint32_t* c, const uint32_t* a, uint32_t b0, uint32_t b1) {
    asm volatile(
        "mma.sync.aligned.m16n8k16.row.col.f16.f16.f16.f16 "
        "{%0,%1},{%2,%3,%4,%5},{%6,%7},{%0,%1};\n"
        : "+r"(c[0]), "+r"(c[1])
        : "r"(a[0]), "r"(a[1]), "r"(a[2]), "r"(a[3]), "r"(b0), "r"(b1));
}
__device__ __forceinline__ void ldsm4(uint32_t& r0, uint32_t& r1, uint32_t& r2, uint32_t& r3,
                                      const void* p) {
    uint32_t a = (uint32_t)__cvta_generic_to_shared(p);
    asm volatile("ldmatrix.sync.aligned.m8n8.x4.shared.b16 {%0,%1,%2,%3}, [%4];\n"
                 : "=r"(r0), "=r"(r1), "=r"(r2), "=r"(r3) : "r"(a));
}
__device__ __forceinline__ void ldsm4t(uint32_t& r0, uint32_t& r1, uint32_t& r2, uint32_t& r3,
                                       const void* p) {
    uint32_t a = (uint32_t)__cvta_generic_to_shared(p);
    asm volatile("ldmatrix.sync.aligned.m8n8.x4.trans.shared.b16 {%0,%1,%2,%3}, [%4];\n"
                 : "=r"(r0), "=r"(r1), "=r"(r2), "=r"(r3) : "r"(a));
}

// ---------------------------------------------------------------------------
// Kernel 1: group-norm statistics (blocks 0..127, float4 loads) + weight fp16
// conversion (blocks 128..1151) fused into one launch.
// ---------------------------------------------------------------------------
__global__ void stats_wconv_kernel(const float* __restrict__ x,
                                   const float* __restrict__ wq,
                                   const float* __restrict__ wp) {
    if (blockIdx.x >= 128) {
        int i = (blockIdx.x - 128) * 256 + threadIdx.x;  // float4 granularity
        const int NQ = CC * 3 * CC / 4;                  // 196608
        if (i < NQ) {
            float4 v = ((const float4*)wq)[i];
            uint2 o; o.x = pkh(v.x, v.y); o.y = pkh(v.z, v.w);
            ((uint2*)g_wqkvh)[i] = o;
        } else {
            int j = i - NQ;                               // < 65536
            float4 v = ((const float4*)wp)[j];
            uint2 o; o.x = pkh(v.x, v.y); o.y = pkh(v.z, v.w);
            ((uint2*)g_wprojh)[j] = o;
        }
        return;
    }
    int bg = blockIdx.x;
    int b = bg / GG, g = bg % GG;
    const float* base = x + (size_t)b * SS * CC + g * 16;
    float sum = 0.f, sq = 0.f;
    for (int i = threadIdx.x; i < SS * 4; i += blockDim.x) {
        int s = i >> 2, c4 = i & 3;
        float4 v = *(const float4*)(base + (size_t)s * CC + c4 * 4);
        sum += v.x + v.y + v.z + v.w;
        sq += v.x * v.x + v.y * v.y + v.z * v.z + v.w * v.w;
    }
    __shared__ float s1[256], s2[256];
    int tid = threadIdx.x;
    s1[tid] = sum; s2[tid] = sq;
    __syncthreads();
    for (int off = 128; off > 0; off >>= 1) {
        if (tid < off) { s1[tid] += s1[tid + off]; s2[tid] += s2[tid + off]; }
        __syncthreads();
    }
    if (tid == 0) {
        float n = (float)(SS * 16);
        float mean = s1[0] / n;
        float var = s2[0] / n - mean * mean;
        g_mean[bg] = mean;
        g_rstd[bg] = rsqrtf(var + EPS);
    }
}

// ---------------------------------------------------------------------------
// Kernel 2: normalize + affine -> g_xnh (fp16)
// ---------------------------------------------------------------------------
__global__ void norm_kernel(const float* __restrict__ x,
                            const float* __restrict__ gamma,
                            const float* __restrict__ beta) {
    size_t i = (size_t)blockIdx.x * blockDim.x + threadIdx.x;
    size_t total = (size_t)BB * SS * CC / 4;
    if (i >= total) return;
    size_t e = i * 4;
    int c = (int)(e % CC);
    int b = (int)(e / ((size_t)SS * CC));
    int bg = b * GG + c / 16;
    float mean = g_mean[bg], rstd = g_rstd[bg];
    float4 xv = ((const float4*)x)[i];
    float4 gv = ((const float4*)gamma)[c / 4];
    float4 bv = ((const float4*)beta)[c / 4];
    uint2 o;
    o.x = pkh((xv.x - mean) * rstd * gv.x + bv.x, (xv.y - mean) * rstd * gv.y + bv.y);
    o.y = pkh((xv.z - mean) * rstd * gv.z + bv.z, (xv.w - mean) * rstd * gv.w + bv.w);
    ((uint2*)g_xnh)[i] = o;
}

// ---------------------------------------------------------------------------
// fp16 tensor-core GEMM (f32 accumulate — R8 champion config):
// C[8192 x N] = A[8192 x 512] @ Bw[512 x N]
// BM=128, BN=128, BK=32; 8 warps (4x2), warp tile 32x64; mma.m16n8k16.f16.f32.
// 3-stage cp.async ring, one __syncthreads per k-tile.
// MODE 0 (QKV): epilogue -> fp16 (Q scaled log2e/8) into g_qh/g_kh/g_vh.
// MODE 1 (PROJ): epilogue adds bias + residual, fp32 to outp.
// ---------------------------------------------------------------------------
#define HASTR 40
#define HBSTR 136
#define HASZ (128 * HASTR)
#define HBSZ (32 * HBSTR)
#define HGEMM_SMEM ((3 * HASZ + 3 * HBSZ) * 2)

template<int N, int MODE>
__global__ void __launch_bounds__(256, 2) h_gemm(
    const float* __restrict__ bias,
    const float* __restrict__ xres, float* __restrict__ outp) {
    extern __shared__ __half smh[];
    __half* As = smh;
    __half* Bs = smh + 3 * HASZ;

    const __half* Ag = (MODE == 1) ? g_aoh : g_xnh;
    const __half* Bw = (MODE == 1) ? g_wprojh : g_wqkvh;
    int m0 = blockIdx.y * 128, n0 = blockIdx.x * 128;
    int tid = threadIdx.x;
    int w = tid >> 5, lane = tid & 31;
    int g = lane >> 2, c = lane & 3;
    int wm = w >> 1, wn = w & 1;
    int mat = lane >> 3, lrow = lane & 7;
    int ro = ((mat & 1) << 3) + lrow;
    int co = (mat >> 1) << 3;

    float acc[2][8][4];
#pragma unroll
    for (int mt = 0; mt < 2; mt++)
#pragma unroll
        for (int nt = 0; nt < 8; nt++)
#pragma unroll
            for (int q = 0; q < 4; q++) acc[mt][nt][q] = 0.f;

    int ar0 = tid >> 1, asg = (tid & 1) * 2;
    int br = tid >> 3, bsg = (tid & 7) * 2;

#pragma unroll
    for (int j0 = 0; j0 < 2; j0++) {
        int k0 = j0 * 32;
        cp16(&As[j0 * HASZ + ar0 * HASTR + asg * 8],
             &Ag[(size_t)(m0 + ar0) * CC + k0 + asg * 8]);
        cp16(&As[j0 * HASZ + ar0 * HASTR + asg * 8 + 8],
             &Ag[(size_t)(m0 + ar0) * CC + k0 + asg * 8 + 8]);
        cp16(&Bs[j0 * HBSZ + br * HBSTR + bsg * 8],
             &Bw[(size_t)(k0 + br) * N + n0 + bsg * 8]);
        cp16(&Bs[j0 * HBSZ + br * HBSTR + bsg * 8 + 8],
             &Bw[(size_t)(k0 + br) * N + n0 + bsg * 8 + 8]);
        cp_commit();
    }

    int st_r = 0, st_w = 2;
    for (int kt = 0; kt < 16; kt++) {
        if (kt < 15) {
            asm volatile("cp.async.wait_group 1;\n");
        } else {
            asm volatile("cp.async.wait_group 0;\n");
        }
        __syncthreads();

        if (kt + 2 < 16) {
            int k0 = (kt + 2) * 32;
            cp16(&As[st_w * HASZ + ar0 * HASTR + asg * 8],
                 &Ag[(size_t)(m0 + ar0) * CC + k0 + asg * 8]);
            cp16(&As[st_w * HASZ + ar0 * HASTR + asg * 8 + 8],
                 &Ag[(size_t)(m0 + ar0) * CC + k0 + asg * 8 + 8]);
            cp16(&Bs[st_w * HBSZ + br * HBSTR + bsg * 8],
                 &Bw[(size_t)(k0 + br) * N + n0 + bsg * 8]);
            cp16(&Bs[st_w * HBSZ + br * HBSTR + bsg * 8 + 8],
                 &Bw[(size_t)(k0 + br) * N + n0 + bsg * 8 + 8]);
            cp_commit();
            st_w++; if (st_w == 3) st_w = 0;
        }

        const __half* Ab = As + st_r * HASZ;
        const __half* Bb = Bs + st_r * HBSZ;
        st_r++; if (st_r == 3) st_r = 0;

#pragma unroll
        for (int ks = 0; ks < 2; ks++) {
            uint32_t af[2][4];
#pragma unroll
            for (int mt = 0; mt < 2; mt++) {
                ldsm4(af[mt][0], af[mt][1], af[mt][2], af[mt][3],
                      &Ab[(wm * 32 + mt * 16 + ro) * HASTR + ks * 16 + co]);
            }
#pragma unroll
            for (int np = 0; np < 4; np++) {
                uint32_t r0, r1, r2, r3;
                ldsm4t(r0, r1, r2, r3,
                       &Bb[(ks * 16 + ro) * HBSTR + wn * 64 + np * 16 + co]);
                mma16816h(acc[0][2 * np], af[0], r0, r1);
                mma16816h(acc[0][2 * np + 1], af[0], r2, r3);
                mma16816h(acc[1][2 * np], af[1], r0, r1);
                mma16816h(acc[1][2 * np + 1], af[1], r2, r3);
            }
        }
    }

    // epilogue
    if (MODE == 1) {
#pragma unroll
        for (int mt = 0; mt < 2; mt++) {
#pragma unroll
            for (int nt = 0; nt < 8; nt++) {
                int row = m0 + wm * 32 + mt * 16 + g;
                int col = n0 + wn * 64 + nt * 8 + 2 * c;
                size_t i0 = (size_t)row * N + col;
                size_t i1 = (size_t)(row + 8) * N + col;
                float2 r0, r1;
                r0.x = acc[mt][nt][0] + bias[col] + xres[i0];
                r0.y = acc[mt][nt][1] + bias[col + 1] + xres[i0 + 1];
                r1.x = acc[mt][nt][2] + bias[col] + xres[i1];
                r1.y = acc[mt][nt][3] + bias[col + 1] + xres[i1 + 1];
                *(float2*)&outp[i0] = r0;
                *(float2*)&outp[i1] = r1;
            }
        }
    } else {
        int sec = n0 >> 9;                 // 0=Q 1=K 2=V
        float scl = (sec == 0) ? 0.18033688f : 1.f;  // 0.125 * log2(e)
        __half* dst = (sec == 0) ? g_qh : ((sec == 1) ? g_kh : g_vh);
        int fbase = n0 & 511;
#pragma unroll
        for (int mt = 0; mt < 2; mt++) {
#pragma unroll
            for (int nt = 0; nt < 8; nt++) {
                int row = m0 + wm * 32 + mt * 16 + g;
                int fh = fbase + wn * 64 + nt * 8 + 2 * c;
                int h = fh >> 6, d = fh & 63;
                int bb = row >> 11, s = row & 2047;
                size_t base = (((size_t)bb * HH + h) * SS + s) * DD + d;
                *(uint32_t*)&dst[base] = pkh(acc[mt][nt][0] * scl, acc[mt][nt][1] * scl);
                *(uint32_t*)&dst[base + 8 * DD] = pkh(acc[mt][nt][2] * scl, acc[mt][nt][3] * scl);
            }
        }
    }
}

// ---------------------------------------------------------------------------
// Kernel 5: fused flash attention v3 — occupancy push (3 CTAs/SM).
// 8 warps = 4 row-groups (wr) x 2 key-groups (wc); Q frags RELOADED from smem
// each iteration (no register cache); QK scores accumulate in packed f16 ->
// ex2.f16x2 in place -> PV A-fragments verbatim. O accum f16 partials; lsum
// f32 via ones-B mma. __launch_bounds__(256,3) caps regs at 84.
// Br=128, Bc=64, D=64; 3-stage cp.async ring, one barrier per iteration.
// ---------------------------------------------------------------------------
#define FPAD 72
#define KSTG (64 * FPAD)
#define FLASH_SMEM ((128 * FPAD + 3 * KSTG + 3 * KSTG) * 2)
#define ONESH2 0x3C003C00u

__global__ void __launch_bounds__(256, 3) flash_kernel() {
    extern __shared__ __half smf[];
    __half* Qs = smf;
    __half* Ks = Qs + 128 * FPAD;
    __half* Vs = Ks + 3 * KSTG;

    int tid = threadIdx.x;
    int w = tid >> 5, lane = tid & 31;
    int g = lane >> 2, c = lane & 3;
    int wr = w & 3, wc = w >> 2;
    int bh = blockIdx.y;
    int m0 = blockIdx.x * 128;

    int mat = lane >> 3, lrow = lane & 7;
    int ro = ((mat & 1) << 3) + lrow;
    int co = (mat >> 1) << 3;

    const __half* Qg = g_qh + (size_t)bh * SS * DD + (size_t)m0 * DD;
    const __half* Kg = g_kh + (size_t)bh * SS * DD;
    const __half* Vg = g_vh + (size_t)bh * SS * DD;

    int prow0 = tid >> 3, psg = tid & 7;
    int prow1 = prow0 + 32;

#pragma unroll
    for (int j0 = 0; j0 < 2; j0++) {
        const __half* kp = Kg + (size_t)j0 * 64 * 64;
        const __half* vp = Vg + (size_t)j0 * 64 * 64;
        cp16(&Ks[j0 * KSTG + prow0 * FPAD + psg * 8], kp + prow0 * 64 + psg * 8);
        cp16(&Ks[j0 * KSTG + prow1 * FPAD + psg * 8], kp + prow1 * 64 + psg * 8);
        cp16(&Vs[j0 * KSTG + prow0 * FPAD + psg * 8], vp + prow0 * 64 + psg * 8);
        cp16(&Vs[j0 * KSTG + prow1 * FPAD + psg * 8], vp + prow1 * 64 + psg * 8);
        cp_commit();
    }
#pragma unroll
    for (int p = 0; p < 4; p++) {
        int i = tid + p * 256;
        int row = i >> 3, sg = i & 7;
        *(float4*)&Qs[row * FPAD + sg * 8] = *(const float4*)(Qg + row * 64 + sg * 8);
    }
    __syncthreads();

    uint32_t oc[2][8][2];   // f16 partial O (this warp's key half)
#pragma unroll
    for (int mt = 0; mt < 2; mt++)
#pragma unroll
        for (int nt = 0; nt < 8; nt++) { oc[mt][nt][0] = 0u; oc[mt][nt][1] = 0u; }
    float lsumf[2][4];
#pragma unroll
    for (int mt = 0; mt < 2; mt++)
#pragma unroll
        for (int q = 0; q < 4; q++) lsumf[mt][q] = 0.f;

    int st_r = 0, st_w = 2;
    for (int j = 0; j < 32; j++) {
        if (j < 31) {
            asm volatile("cp.async.wait_group 1;\n");
        } else {
            asm volatile("cp.async.wait_group 0;\n");
        }
        __syncthreads();

        if (j + 2 < 32) {
            const __half* kp = Kg + (size_t)(j + 2) * 64 * 64;
            const __half* vp = Vg + (size_t)(j + 2) * 64 * 64;
            cp16(&Ks[st_w * KSTG + prow0 * FPAD + psg * 8], kp + prow0 * 64 + psg * 8);
            cp16(&Ks[st_w * KSTG + prow1 * FPAD + psg * 8], kp + prow1 * 64 + psg * 8);
            cp16(&Vs[st_w * KSTG + prow0 * FPAD + psg * 8], vp + prow0 * 64 + psg * 8);
            cp16(&Vs[st_w * KSTG + prow1 * FPAD + psg * 8], vp + prow1 * 64 + psg * 8);
            cp_commit();
            st_w++; if (st_w == 3) st_w = 0;
        }

        const __half* Kb = Ks + st_r * KSTG;
        const __half* Vb = Vs + st_r * KSTG;
        st_r++; if (st_r == 3) st_r = 0;

        // S = Q @ K^T over this warp's 32 keys (exp2-domain, f16 packed accum).
        // Q fragments reloaded from smem via ldsm each iteration.
        uint32_t sc[2][4][2];
#pragma unroll
        for (int mt = 0; mt < 2; mt++)
#pragma unroll
            for (int nt = 0; nt < 4; nt++) { sc[mt][nt][0] = 0u; sc[mt][nt][1] = 0u; }
#pragma unroll
        for (int ks = 0; ks < 4; ks++) {
            uint32_t qf[2][4];
#pragma unroll
            for (int mt = 0; mt < 2; mt++) {
                ldsm4(qf[mt][0], qf[mt][1], qf[mt][2], qf[mt][3],
                      &Qs[(wr * 32 + mt * 16 + ro) * FPAD + ks * 16 + co]);
            }
#pragma unroll
            for (int np = 0; np < 2; np++) {
                uint32_t r0, r1, r2, r3;
                ldsm4(r0, r1, r2, r3, &Kb[(wc * 32 + np * 16 + ro) * FPAD + ks * 16 + co]);
                mma16816hh(sc[0][2 * np], qf[0], r0, r2);
                mma16816hh(sc[0][2 * np + 1], qf[0], r1, r3);
                mma16816hh(sc[1][2 * np], qf[1], r0, r2);
                mma16816hh(sc[1][2 * np + 1], qf[1], r1, r3);
            }
        }

        // P = 2^S in place (packed f16)
#pragma unroll
        for (int mt = 0; mt < 2; mt++)
#pragma unroll
            for (int nt = 0; nt < 4; nt++) {
                sc[mt][nt][0] = ex2h2(sc[mt][nt][0]);
                sc[mt][nt][1] = ex2h2(sc[mt][nt][1]);
            }

        // PV over this warp's 32 keys; PV A-fragments are sc registers verbatim
#pragma unroll
        for (int kp = 0; kp < 2; kp++) {
            uint32_t pa[2][4];
#pragma unroll
            for (int mt = 0; mt < 2; mt++) {
                pa[mt][0] = sc[mt][2 * kp][0];
                pa[mt][1] = sc[mt][2 * kp][1];
                pa[mt][2] = sc[mt][2 * kp + 1][0];
                pa[mt][3] = sc[mt][2 * kp + 1][1];
                mma16816h(lsumf[mt], pa[mt], ONESH2, ONESH2);
            }
#pragma unroll
            for (int np = 0; np < 4; np++) {
                uint32_t r0, r1, r2, r3;
                ldsm4t(r0, r1, r2, r3, &Vb[(wc * 32 + kp * 16 + ro) * FPAD + np * 16 + co]);
                mma16816hh(oc[0][2 * np], pa[0], r0, r1);
                mma16816hh(oc[0][2 * np + 1], pa[0], r2, r3);
                mma16816hh(oc[1][2 * np], pa[1], r0, r1);
                mma16816hh(oc[1][2 * np + 1], pa[1], r2, r3);
            }
        }
    }

    // cross-warp partial-sum: wc==1 stores partials, wc==0 combines + writes
    __syncthreads();
    __half* osm = Ks;                       // 128 x FPAD halves (reuse KV space)
    float* lsums = (float*)Vs;              // 128 floats
    if (wc == 1) {
#pragma unroll
        for (int mt = 0; mt < 2; mt++) {
            int rb = wr * 32 + mt * 16;
#pragma unroll
            for (int nt = 0; nt < 8; nt++) {
                *(uint32_t*)&osm[(rb + g) * FPAD + nt * 8 + 2 * c] = oc[mt][nt][0];
                *(uint32_t*)&osm[(rb + g + 8) * FPAD + nt * 8 + 2 * c] = oc[mt][nt][1];
            }
            if (c == 0) {
                lsums[rb + g] = lsumf[mt][0];
                lsums[rb + g + 8] = lsumf[mt][2];
            }
        }
    }
    __syncthreads();
    if (wc == 0) {
        int b = bh >> 3, h = bh & 7;
#pragma unroll
        for (int mt = 0; mt < 2; mt++) {
            int rb = wr * 32 + mt * 16;
            float l0 = lsumf[mt][0] + lsums[rb + g];
            float l1 = lsumf[mt][2] + lsums[rb + g + 8];
            float inv0 = 1.f / l0, inv1 = 1.f / l1;
            __half* Ob = g_aoh + ((size_t)b * SS + m0 + rb) * CC + h * 64;
#pragma unroll
            for (int nt = 0; nt < 8; nt++) {
                __half2 own0 = *reinterpret_cast<__half2*>(&oc[mt][nt][0]);
                __half2 own1 = *reinterpret_cast<__half2*>(&oc[mt][nt][1]);
                __half2 p0 = *(__half2*)&osm[(rb + g) * FPAD + nt * 8 + 2 * c];
                __half2 p1 = *(__half2*)&osm[(rb + g + 8) * FPAD + nt * 8 + 2 * c];
                float o00 = __half2float(own0.x) + __half2float(p0.x);
                float o01 = __half2float(own0.y) + __half2float(p0.y);
                float o10 = __half2float(own1.x) + __half2float(p1.x);
                float o11 = __half2float(own1.y) + __half2float(p1.y);
                *(uint32_t*)&Ob[(size_t)g * CC + nt * 8 + 2 * c] = pkh(o00 * inv0, o01 * inv0);
                *(uint32_t*)&Ob[(size_t)(g + 8) * CC + nt * 8 + 2 * c] = pkh(o10 * inv1, o11 * inv1);
            }
        }
    }
}

// ---------------------------------------------------------------------------
extern "C" void kernel_launch(void* const* d_in, const int* in_sizes, int n_in,
                              void* d_out, int out_size) {
    (void)in_sizes; (void)n_in; (void)out_size;
    const float* x      = (const float*)d_in[0];
    const float* gamma  = (const float*)d_in[1];
    const float* beta   = (const float*)d_in[2];
    const float* w_qkv  = (const float*)d_in[3];
    const float* w_proj = (const float*)d_in[4];
    const float* b_proj = (const float*)d_in[5];
    float* out = (float*)d_out;

    static int attr_set = 0;
    if (!attr_set) {
        cudaFuncSetAttribute(flash_kernel,
                             cudaFuncAttributeMaxDynamicSharedMemorySize, FLASH_SMEM);
        cudaFuncSetAttribute(h_gemm<1536, 0>,
                             cudaFuncAttributeMaxDynamicSharedMemorySize, HGEMM_SMEM);
        cudaFuncSetAttribute(h_gemm<512, 1>,
                             cudaFuncAttributeMaxDynamicSharedMemorySize, HGEMM_SMEM);
        attr_set = 1;
    }

    stats_wconv_kernel<<<128 + 1024, 256>>>(x, w_qkv, w_proj);

    size_t nvec = (size_t)BB * SS * CC / 4;
    norm_kernel<<<(unsigned)((nvec + 255) / 256), 256>>>(x, gamma, beta);

    h_gemm<1536, 0><<<dim3(1536 / 128, (BB * SS) / 128), 256, HGEMM_SMEM>>>(
        nullptr, nullptr, nullptr);

    flash_kernel<<<dim3(SS / 128, BB * HH), 256, FLASH_SMEM>>>();

    h_gemm<512, 1><<<dim3(512 / 128, (BB * SS) / 128), 256, HGEMM_SMEM>>>(
        b_proj, x, out);
}

// round 16
// speedup vs baseline: 1.0122x; 1.0122x over previous
#include <cuda_runtime.h>
#include <cuda_bf16.h>
#include <cuda_fp16.h>
#include <math.h>
#include <stdint.h>

// Problem constants
#define BB 4
#define SS 2048
#define CC 512
#define HH 8
#define GG 32
#define DD 64
#define EPS 1e-3f

// Scratch (device globals; allocation-free per harness rules)
__device__ float g_mean[BB * GG];
__device__ float g_rstd[BB * GG];
__device__ __half g_xnh[(size_t)BB * SS * CC];        // fp16 normalized input
__device__ __half g_aoh[(size_t)BB * SS * CC];        // fp16 attention out
__device__ __half g_wqkvh[(size_t)CC * 3 * CC];       // [512 x 1536] fp16
__device__ __half g_wprojh[(size_t)CC * CC];          // [512 x 512] fp16
__device__ __half g_qh[(size_t)BB * HH * SS * DD];    // (pre-scaled by log2e/8)
__device__ __half g_kh[(size_t)BB * HH * SS * DD];
__device__ __half g_vh[(size_t)BB * HH * SS * DD];    // [bh][s][d]

// ---------------------------------------------------------------------------
// helpers
// ---------------------------------------------------------------------------
__device__ __forceinline__ void cp16(void* s, const void* g) {
    unsigned sa = (unsigned)__cvta_generic_to_shared(s);
    asm volatile("cp.async.cg.shared.global [%0], [%1], 16;\n" :: "r"(sa), "l"(g));
}
__device__ __forceinline__ void cp_commit() {
    asm volatile("cp.async.commit_group;\n");
}
__device__ __forceinline__ uint32_t pkh(float x, float y) {
    __half2 t = __floats2half2_rn(x, y);
    return *reinterpret_cast<uint32_t*>(&t);
}
__device__ __forceinline__ uint32_t ex2h2(uint32_t x) {
    uint32_t y;
    asm("ex2.approx.f16x2 %0, %1;\n" : "=r"(y) : "r"(x));
    return y;
}
__device__ __forceinline__ void mma16816h(float* c, const uint32_t* a, uint32_t b0, uint32_t b1) {
    asm volatile(
        "mma.sync.aligned.m16n8k16.row.col.f32.f16.f16.f32 "
        "{%0,%1,%2,%3},{%4,%5,%6,%7},{%8,%9},{%0,%1,%2,%3};\n"
        : "+f"(c[0]), "+f"(c[1]), "+f"(c[2]), "+f"(c[3])
        : "r"(a[0]), "r"(a[1]), "r"(a[2]), "r"(a[3]), "r"(b0), "r"(b1));
}
// f16-accum mma: C/D packed half2 x2 (reg0 = row g, reg1 = row g+8)
__device__ __forceinline__ void mma16816hh(uint32_t* c, const uint32_t* a, uint32_t b0, uint32_t b1) {
    asm volatile(
        "mma.sync.aligned.m16n8k16.row.col.f16.f16.f16.f16 "
        "{%0,%1},{%2,%3,%4,%5},{%6,%7},{%0,%1};\n"
        : "+r"(c[0]), "+r"(c[1])
        : "r"(a[0]), "r"(a[1]), "r"(a[2]), "r"(a[3]), "r"(b0), "r"(b1));
}
__device__ __forceinline__ void ldsm4(uint32_t& r0, uint32_t& r1, uint32_t& r2, uint32_t& r3,
                                      const void* p) {
    uint32_t a = (uint32_t)__cvta_generic_to_shared(p);
    asm volatile("ldmatrix.sync.aligned.m8n8.x4.shared.b16 {%0,%1,%2,%3}, [%4];\n"
                 : "=r"(r0), "=r"(r1), "=r"(r2), "=r"(r3) : "r"(a));
}
__device__ __forceinline__ void ldsm4t(uint32_t& r0, uint32_t& r1, uint32_t& r2, uint32_t& r3,
                                       const void* p) {
    uint32_t a = (uint32_t)__cvta_generic_to_shared(p);
    asm volatile("ldmatrix.sync.aligned.m8n8.x4.trans.shared.b16 {%0,%1,%2,%3}, [%4];\n"
                 : "=r"(r0), "=r"(r1), "=r"(r2), "=r"(r3) : "r"(a));
}
__device__ __forceinline__ float qsum(float v) {
    v += __shfl_xor_sync(0xffffffffu, v, 1);
    v += __shfl_xor_sync(0xffffffffu, v, 2);
    return v;
}

// ---------------------------------------------------------------------------
// Kernel 1: group-norm statistics (blocks 0..127, float4 loads) + weight fp16
// conversion (blocks 128..1151) fused into one launch.
// ---------------------------------------------------------------------------
__global__ void stats_wconv_kernel(const float* __restrict__ x,
                                   const float* __restrict__ wq,
                                   const float* __restrict__ wp) {
    if (blockIdx.x >= 128) {
        int i = (blockIdx.x - 128) * 256 + threadIdx.x;  // float4 granularity
        const int NQ = CC * 3 * CC / 4;                  // 196608
        if (i < NQ) {
            float4 v = ((const float4*)wq)[i];
            uint2 o; o.x = pkh(v.x, v.y); o.y = pkh(v.z, v.w);
            ((uint2*)g_wqkvh)[i] = o;
        } else {
            int j = i - NQ;                               // < 65536
            float4 v = ((const float4*)wp)[j];
            uint2 o; o.x = pkh(v.x, v.y); o.y = pkh(v.z, v.w);
            ((uint2*)g_wprojh)[j] = o;
        }
        return;
    }
    int bg = blockIdx.x;
    int b = bg / GG, g = bg % GG;
    const float* base = x + (size_t)b * SS * CC + g * 16;
    float sum = 0.f, sq = 0.f;
    for (int i = threadIdx.x; i < SS * 4; i += blockDim.x) {
        int s = i >> 2, c4 = i & 3;
        float4 v = *(const float4*)(base + (size_t)s * CC + c4 * 4);
        sum += v.x + v.y + v.z + v.w;
        sq += v.x * v.x + v.y * v.y + v.z * v.z + v.w * v.w;
    }
    __shared__ float s1[256], s2[256];
    int tid = threadIdx.x;
    s1[tid] = sum; s2[tid] = sq;
    __syncthreads();
    for (int off = 128; off > 0; off >>= 1) {
        if (tid < off) { s1[tid] += s1[tid + off]; s2[tid] += s2[tid + off]; }
        __syncthreads();
    }
    if (tid == 0) {
        float n = (float)(SS * 16);
        float mean = s1[0] / n;
        float var = s2[0] / n - mean * mean;
        g_mean[bg] = mean;
        g_rstd[bg] = rsqrtf(var + EPS);
    }
}

// ---------------------------------------------------------------------------
// Kernel 2: normalize + affine -> g_xnh (fp16)
// ---------------------------------------------------------------------------
__global__ void norm_kernel(const float* __restrict__ x,
                            const float* __restrict__ gamma,
                            const float* __restrict__ beta) {
    size_t i = (size_t)blockIdx.x * blockDim.x + threadIdx.x;
    size_t total = (size_t)BB * SS * CC / 4;
    if (i >= total) return;
    size_t e = i * 4;
    int c = (int)(e % CC);
    int b = (int)(e / ((size_t)SS * CC));
    int bg = b * GG + c / 16;
    float mean = g_mean[bg], rstd = g_rstd[bg];
    float4 xv = ((const float4*)x)[i];
    float4 gv = ((const float4*)gamma)[c / 4];
    float4 bv = ((const float4*)beta)[c / 4];
    uint2 o;
    o.x = pkh((xv.x - mean) * rstd * gv.x + bv.x, (xv.y - mean) * rstd * gv.y + bv.y);
    o.y = pkh((xv.z - mean) * rstd * gv.z + bv.z, (xv.w - mean) * rstd * gv.w + bv.w);
    ((uint2*)g_xnh)[i] = o;
}

// ---------------------------------------------------------------------------
// fp16 tensor-core GEMM (f32 accumulate — R8 champion config):
// C[8192 x N] = A[8192 x 512] @ Bw[512 x N]
// BM=128, BN=128, BK=32; 8 warps (4x2), warp tile 32x64; mma.m16n8k16.f16.f32.
// 3-stage cp.async ring, one __syncthreads per k-tile.
// MODE 0 (QKV): epilogue -> fp16 (Q scaled log2e/8) into g_qh/g_kh/g_vh.
// MODE 1 (PROJ): epilogue adds bias + residual, fp32 to outp.
// ---------------------------------------------------------------------------
#define HASTR 40
#define HBSTR 136
#define HASZ (128 * HASTR)
#define HBSZ (32 * HBSTR)
#define HGEMM_SMEM ((3 * HASZ + 3 * HBSZ) * 2)

template<int N, int MODE>
__global__ void __launch_bounds__(256, 2) h_gemm(
    const float* __restrict__ bias,
    const float* __restrict__ xres, float* __restrict__ outp) {
    extern __shared__ __half smh[];
    __half* As = smh;
    __half* Bs = smh + 3 * HASZ;

    const __half* Ag = (MODE == 1) ? g_aoh : g_xnh;
    const __half* Bw = (MODE == 1) ? g_wprojh : g_wqkvh;
    int m0 = blockIdx.y * 128, n0 = blockIdx.x * 128;
    int tid = threadIdx.x;
    int w = tid >> 5, lane = tid & 31;
    int g = lane >> 2, c = lane & 3;
    int wm = w >> 1, wn = w & 1;
    int mat = lane >> 3, lrow = lane & 7;
    int ro = ((mat & 1) << 3) + lrow;
    int co = (mat >> 1) << 3;

    float acc[2][8][4];
#pragma unroll
    for (int mt = 0; mt < 2; mt++)
#pragma unroll
        for (int nt = 0; nt < 8; nt++)
#pragma unroll
            for (int q = 0; q < 4; q++) acc[mt][nt][q] = 0.f;

    int ar0 = tid >> 1, asg = (tid & 1) * 2;
    int br = tid >> 3, bsg = (tid & 7) * 2;

#pragma unroll
    for (int j0 = 0; j0 < 2; j0++) {
        int k0 = j0 * 32;
        cp16(&As[j0 * HASZ + ar0 * HASTR + asg * 8],
             &Ag[(size_t)(m0 + ar0) * CC + k0 + asg * 8]);
        cp16(&As[j0 * HASZ + ar0 * HASTR + asg * 8 + 8],
             &Ag[(size_t)(m0 + ar0) * CC + k0 + asg * 8 + 8]);
        cp16(&Bs[j0 * HBSZ + br * HBSTR + bsg * 8],
             &Bw[(size_t)(k0 + br) * N + n0 + bsg * 8]);
        cp16(&Bs[j0 * HBSZ + br * HBSTR + bsg * 8 + 8],
             &Bw[(size_t)(k0 + br) * N + n0 + bsg * 8 + 8]);
        cp_commit();
    }

    int st_r = 0, st_w = 2;
    for (int kt = 0; kt < 16; kt++) {
        if (kt < 15) {
            asm volatile("cp.async.wait_group 1;\n");
        } else {
            asm volatile("cp.async.wait_group 0;\n");
        }
        __syncthreads();

        if (kt + 2 < 16) {
            int k0 = (kt + 2) * 32;
            cp16(&As[st_w * HASZ + ar0 * HASTR + asg * 8],
                 &Ag[(size_t)(m0 + ar0) * CC + k0 + asg * 8]);
            cp16(&As[st_w * HASZ + ar0 * HASTR + asg * 8 + 8],
                 &Ag[(size_t)(m0 + ar0) * CC + k0 + asg * 8 + 8]);
            cp16(&Bs[st_w * HBSZ + br * HBSTR + bsg * 8],
                 &Bw[(size_t)(k0 + br) * N + n0 + bsg * 8]);
            cp16(&Bs[st_w * HBSZ + br * HBSTR + bsg * 8 + 8],
                 &Bw[(size_t)(k0 + br) * N + n0 + bsg * 8 + 8]);
            cp_commit();
            st_w++; if (st_w == 3) st_w = 0;
        }

        const __half* Ab = As + st_r * HASZ;
        const __half* Bb = Bs + st_r * HBSZ;
        st_r++; if (st_r == 3) st_r = 0;

#pragma unroll
        for (int ks = 0; ks < 2; ks++) {
            uint32_t af[2][4];
#pragma unroll
            for (int mt = 0; mt < 2; mt++) {
                ldsm4(af[mt][0], af[mt][1], af[mt][2], af[mt][3],
                      &Ab[(wm * 32 + mt * 16 + ro) * HASTR + ks * 16 + co]);
            }
#pragma unroll
            for (int np = 0; np < 4; np++) {
                uint32_t r0, r1, r2, r3;
                ldsm4t(r0, r1, r2, r3,
                       &Bb[(ks * 16 + ro) * HBSTR + wn * 64 + np * 16 + co]);
                mma16816h(acc[0][2 * np], af[0], r0, r1);
                mma16816h(acc[0][2 * np + 1], af[0], r2, r3);
                mma16816h(acc[1][2 * np], af[1], r0, r1);
                mma16816h(acc[1][2 * np + 1], af[1], r2, r3);
            }
        }
    }

    // epilogue
    if (MODE == 1) {
#pragma unroll
        for (int mt = 0; mt < 2; mt++) {
#pragma unroll
            for (int nt = 0; nt < 8; nt++) {
                int row = m0 + wm * 32 + mt * 16 + g;
                int col = n0 + wn * 64 + nt * 8 + 2 * c;
                size_t i0 = (size_t)row * N + col;
                size_t i1 = (size_t)(row + 8) * N + col;
                float2 r0, r1;
                r0.x = acc[mt][nt][0] + bias[col] + xres[i0];
                r0.y = acc[mt][nt][1] + bias[col + 1] + xres[i0 + 1];
                r1.x = acc[mt][nt][2] + bias[col] + xres[i1];
                r1.y = acc[mt][nt][3] + bias[col + 1] + xres[i1 + 1];
                *(float2*)&outp[i0] = r0;
                *(float2*)&outp[i1] = r1;
            }
        }
    } else {
        int sec = n0 >> 9;                 // 0=Q 1=K 2=V
        float scl = (sec == 0) ? 0.18033688f : 1.f;  // 0.125 * log2(e)
        __half* dst = (sec == 0) ? g_qh : ((sec == 1) ? g_kh : g_vh);
        int fbase = n0 & 511;
#pragma unroll
        for (int mt = 0; mt < 2; mt++) {
#pragma unroll
            for (int nt = 0; nt < 8; nt++) {
                int row = m0 + wm * 32 + mt * 16 + g;
                int fh = fbase + wn * 64 + nt * 8 + 2 * c;
                int h = fh >> 6, d = fh & 63;
                int bb = row >> 11, s = row & 2047;
                size_t base = (((size_t)bb * HH + h) * SS + s) * DD + d;
                *(uint32_t*)&dst[base] = pkh(acc[mt][nt][0] * scl, acc[mt][nt][1] * scl);
                *(uint32_t*)&dst[base + 8 * DD] = pkh(acc[mt][nt][2] * scl, acc[mt][nt][3] * scl);
            }
        }
    }
}

// ---------------------------------------------------------------------------
// Kernel 5: fused flash attention v2.1 (R14 base) — lsum moved OFF the tensor
// pipe. 8 warps = 4 row-groups (wr) x 2 key-groups (wc); Q frags cached; QK
// accum f32 -> ex2.f16x2 packed P; O accum f16 partials. Row sums now scalar:
// HADD2 tree on packed P + f32 accumulate (fma pipe), quad-shuffle reduce in
// epilogue. Br=128, Bc=64, D=64; 3-stage cp.async ring, one barrier per iter.
// ---------------------------------------------------------------------------
#define FPAD 72
#define KSTG (64 * FPAD)
#define FLASH_SMEM ((128 * FPAD + 3 * KSTG + 3 * KSTG) * 2)

__global__ void __launch_bounds__(256, 2) flash_kernel() {
    extern __shared__ __half smf[];
    __half* Qs = smf;
    __half* Ks = Qs + 128 * FPAD;
    __half* Vs = Ks + 3 * KSTG;

    int tid = threadIdx.x;
    int w = tid >> 5, lane = tid & 31;
    int g = lane >> 2, c = lane & 3;
    int wr = w & 3, wc = w >> 2;
    int bh = blockIdx.y;
    int m0 = blockIdx.x * 128;

    int mat = lane >> 3, lrow = lane & 7;
    int ro = ((mat & 1) << 3) + lrow;
    int co = (mat >> 1) << 3;

    const __half* Qg = g_qh + (size_t)bh * SS * DD + (size_t)m0 * DD;
    const __half* Kg = g_kh + (size_t)bh * SS * DD;
    const __half* Vg = g_vh + (size_t)bh * SS * DD;

    int prow0 = tid >> 3, psg = tid & 7;
    int prow1 = prow0 + 32;

#pragma unroll
    for (int j0 = 0; j0 < 2; j0++) {
        const __half* kp = Kg + (size_t)j0 * 64 * 64;
        const __half* vp = Vg + (size_t)j0 * 64 * 64;
        cp16(&Ks[j0 * KSTG + prow0 * FPAD + psg * 8], kp + prow0 * 64 + psg * 8);
        cp16(&Ks[j0 * KSTG + prow1 * FPAD + psg * 8], kp + prow1 * 64 + psg * 8);
        cp16(&Vs[j0 * KSTG + prow0 * FPAD + psg * 8], vp + prow0 * 64 + psg * 8);
        cp16(&Vs[j0 * KSTG + prow1 * FPAD + psg * 8], vp + prow1 * 64 + psg * 8);
        cp_commit();
    }
#pragma unroll
    for (int p = 0; p < 4; p++) {
        int i = tid + p * 256;
        int row = i >> 3, sg = i & 7;
        *(float4*)&Qs[row * FPAD + sg * 8] = *(const float4*)(Qg + row * 64 + sg * 8);
    }
    __syncthreads();

    // Q fragments: 32 rows (wr*32 .. +32), cached
    uint32_t qa[2][4][4];
#pragma unroll
    for (int mt = 0; mt < 2; mt++) {
        int rb = wr * 32 + mt * 16;
#pragma unroll
        for (int ks = 0; ks < 4; ks++) {
            int kb = ks * 16;
            qa[mt][ks][0] = *(const uint32_t*)&Qs[(rb + g) * FPAD + kb + 2 * c];
            qa[mt][ks][1] = *(const uint32_t*)&Qs[(rb + g + 8) * FPAD + kb + 2 * c];
            qa[mt][ks][2] = *(const uint32_t*)&Qs[(rb + g) * FPAD + kb + 2 * c + 8];
            qa[mt][ks][3] = *(const uint32_t*)&Qs[(rb + g + 8) * FPAD + kb + 2 * c + 8];
        }
    }

    uint32_t oc[2][8][2];   // f16 partial O (this warp's key half)
#pragma unroll
    for (int mt = 0; mt < 2; mt++)
#pragma unroll
        for (int nt = 0; nt < 8; nt++) { oc[mt][nt][0] = 0u; oc[mt][nt][1] = 0u; }
    float ls0[2] = {0.f, 0.f};   // row g (per mt), lane-local partial
    float ls1[2] = {0.f, 0.f};   // row g+8

    int st_r = 0, st_w = 2;
    for (int j = 0; j < 32; j++) {
        if (j < 31) {
            asm volatile("cp.async.wait_group 1;\n");
        } else {
            asm volatile("cp.async.wait_group 0;\n");
        }
        __syncthreads();

        if (j + 2 < 32) {
            const __half* kp = Kg + (size_t)(j + 2) * 64 * 64;
            const __half* vp = Vg + (size_t)(j + 2) * 64 * 64;
            cp16(&Ks[st_w * KSTG + prow0 * FPAD + psg * 8], kp + prow0 * 64 + psg * 8);
            cp16(&Ks[st_w * KSTG + prow1 * FPAD + psg * 8], kp + prow1 * 64 + psg * 8);
            cp16(&Vs[st_w * KSTG + prow0 * FPAD + psg * 8], vp + prow0 * 64 + psg * 8);
            cp16(&Vs[st_w * KSTG + prow1 * FPAD + psg * 8], vp + prow1 * 64 + psg * 8);
            cp_commit();
            st_w++; if (st_w == 3) st_w = 0;
        }

        const __half* Kb = Ks + st_r * KSTG;
        const __half* Vb = Vs + st_r * KSTG;
        st_r++; if (st_r == 3) st_r = 0;

        // S = Q @ K^T over this warp's 32 keys (exp2-domain, f32 accum)
        float sc[2][4][4];
#pragma unroll
        for (int mt = 0; mt < 2; mt++)
#pragma unroll
            for (int nt = 0; nt < 4; nt++)
#pragma unroll
                for (int q = 0; q < 4; q++) sc[mt][nt][q] = 0.f;
#pragma unroll
        for (int np = 0; np < 2; np++) {
#pragma unroll
            for (int ks = 0; ks < 4; ks++) {
                uint32_t r0, r1, r2, r3;
                ldsm4(r0, r1, r2, r3, &Kb[(wc * 32 + np * 16 + ro) * FPAD + ks * 16 + co]);
                mma16816h(sc[0][2 * np], qa[0][ks], r0, r2);
                mma16816h(sc[0][2 * np + 1], qa[0][ks], r1, r3);
                mma16816h(sc[1][2 * np], qa[1][ks], r0, r2);
                mma16816h(sc[1][2 * np + 1], qa[1][ks], r1, r3);
            }
        }

        // PV over this warp's 32 keys; P = 2^S built on the fly.
        // Row sums: HADD2 tree on packed P + f32 accumulate (fma pipe, not tensor).
#pragma unroll
        for (int kp = 0; kp < 2; kp++) {
            uint32_t pa[2][4];
#pragma unroll
            for (int mt = 0; mt < 2; mt++) {
                pa[mt][0] = ex2h2(pkh(sc[mt][2 * kp][0], sc[mt][2 * kp][1]));
                pa[mt][1] = ex2h2(pkh(sc[mt][2 * kp][2], sc[mt][2 * kp][3]));
                pa[mt][2] = ex2h2(pkh(sc[mt][2 * kp + 1][0], sc[mt][2 * kp + 1][1]));
                pa[mt][3] = ex2h2(pkh(sc[mt][2 * kp + 1][2], sc[mt][2 * kp + 1][3]));
                // row g: pa[0] + pa[2]; row g+8: pa[1] + pa[3]
                __half2 sg = __hadd2(*reinterpret_cast<__half2*>(&pa[mt][0]),
                                     *reinterpret_cast<__half2*>(&pa[mt][2]));
                __half2 sh = __hadd2(*reinterpret_cast<__half2*>(&pa[mt][1]),
                                     *reinterpret_cast<__half2*>(&pa[mt][3]));
                float2 fg = __half22float2(sg);
                float2 fh = __half22float2(sh);
                ls0[mt] += fg.x + fg.y;
                ls1[mt] += fh.x + fh.y;
            }
#pragma unroll
            for (int np = 0; np < 4; np++) {
                uint32_t r0, r1, r2, r3;
                ldsm4t(r0, r1, r2, r3, &Vb[(wc * 32 + kp * 16 + ro) * FPAD + np * 16 + co]);
                mma16816hh(oc[0][2 * np], pa[0], r0, r1);
                mma16816hh(oc[0][2 * np + 1], pa[0], r2, r3);
                mma16816hh(oc[1][2 * np], pa[1], r0, r1);
                mma16816hh(oc[1][2 * np + 1], pa[1], r2, r3);
            }
        }
    }

    // quad-reduce lane-local row sums (all lanes get the value)
#pragma unroll
    for (int mt = 0; mt < 2; mt++) {
        ls0[mt] = qsum(ls0[mt]);
        ls1[mt] = qsum(ls1[mt]);
    }

    // cross-warp partial-sum: wc==1 stores partials, wc==0 combines + writes
    __syncthreads();
    __half* osm = Ks;                       // 128 x FPAD halves (reuse KV space)
    float* lsums = (float*)Vs;              // 128 floats
    if (wc == 1) {
#pragma unroll
        for (int mt = 0; mt < 2; mt++) {
            int rb = wr * 32 + mt * 16;
#pragma unroll
            for (int nt = 0; nt < 8; nt++) {
                *(uint32_t*)&osm[(rb + g) * FPAD + nt * 8 + 2 * c] = oc[mt][nt][0];
                *(uint32_t*)&osm[(rb + g + 8) * FPAD + nt * 8 + 2 * c] = oc[mt][nt][1];
            }
            if (c == 0) {
                lsums[rb + g] = ls0[mt];
                lsums[rb + g + 8] = ls1[mt];
            }
        }
    }
    __syncthreads();
    if (wc == 0) {
        int b = bh >> 3, h = bh & 7;
#pragma unroll
        for (int mt = 0; mt < 2; mt++) {
            int rb = wr * 32 + mt * 16;
            float l0 = ls0[mt] + lsums[rb + g];
            float l1 = ls1[mt] + lsums[rb + g + 8];
            float inv0 = 1.f / l0, inv1 = 1.f / l1;
            __half* Ob = g_aoh + ((size_t)b * SS + m0 + rb) * CC + h * 64;
#pragma unroll
            for (int nt = 0; nt < 8; nt++) {
                __half2 own0 = *reinterpret_cast<__half2*>(&oc[mt][nt][0]);
                __half2 own1 = *reinterpret_cast<__half2*>(&oc[mt][nt][1]);
                __half2 p0 = *(__half2*)&osm[(rb + g) * FPAD + nt * 8 + 2 * c];
                __half2 p1 = *(__half2*)&osm[(rb + g + 8) * FPAD + nt * 8 + 2 * c];
                float o00 = __half2float(own0.x) + __half2float(p0.x);
                float o01 = __half2float(own0.y) + __half2float(p0.y);
                float o10 = __half2float(own1.x) + __half2float(p1.x);
                float o11 = __half2float(own1.y) + __half2float(p1.y);
                *(uint32_t*)&Ob[(size_t)g * CC + nt * 8 + 2 * c] = pkh(o00 * inv0, o01 * inv0);
                *(uint32_t*)&Ob[(size_t)(g + 8) * CC + nt * 8 + 2 * c] = pkh(o10 * inv1, o11 * inv1);
            }
        }
    }
}

// ---------------------------------------------------------------------------
extern "C" void kernel_launch(void* const* d_in, const int* in_sizes, int n_in,
                              void* d_out, int out_size) {
    (void)in_sizes; (void)n_in; (void)out_size;
    const float* x      = (const float*)d_in[0];
    const float* gamma  = (const float*)d_in[1];
    const float* beta   = (const float*)d_in[2];
    const float* w_qkv  = (const float*)d_in[3];
    const float* w_proj = (const float*)d_in[4];
    const float* b_proj = (const float*)d_in[5];
    float* out = (float*)d_out;

    static int attr_set = 0;
    if (!attr_set) {
        cudaFuncSetAttribute(flash_kernel,
                             cudaFuncAttributeMaxDynamicSharedMemorySize, FLASH_SMEM);
        cudaFuncSetAttribute(h_gemm<1536, 0>,
                             cudaFuncAttributeMaxDynamicSharedMemorySize, HGEMM_SMEM);
        cudaFuncSetAttribute(h_gemm<512, 1>,
                             cudaFuncAttributeMaxDynamicSharedMemorySize, HGEMM_SMEM);
        attr_set = 1;
    }

    stats_wconv_kernel<<<128 + 1024, 256>>>(x, w_qkv, w_proj);

    size_t nvec = (size_t)BB * SS * CC / 4;
    norm_kernel<<<(unsigned)((nvec + 255) / 256), 256>>>(x, gamma, beta);

    h_gemm<1536, 0><<<dim3(1536 / 128, (BB * SS) / 128), 256, HGEMM_SMEM>>>(
        nullptr, nullptr, nullptr);

    flash_kernel<<<dim3(SS / 128, BB * HH), 256, HGEMM_SMEM < FLASH_SMEM ? FLASH_SMEM : FLASH_SMEM>>>();

    h_gemm<512, 1><<<dim3(512 / 128, (BB * SS) / 128), 256, HGEMM_SMEM>>>(
        b_proj, x, out);
}